// round 2
// baseline (speedup 1.0000x reference)
#include <cuda_runtime.h>
#include <math.h>

#define BATCH 256
#define LTOK  576
#define DDIM  1024
#define EPSV  1e-8f
#define TOK_PER_BLOCK 8

// scratch: sims[B, L]
__device__ float g_sims[BATCH * LTOK];

// ---------------------------------------------------------------------------
// Kernel 1: cosine sims. One warp per token; 8 tokens (same batch row) per
// block so i_feats[b] is staged in smem once. Fully coalesced float4 streams.
// ---------------------------------------------------------------------------
__global__ __launch_bounds__(256) void sims_kernel(
    const float* __restrict__ ifeat,   // [B, D]
    const float* __restrict__ img)     // [B, L, D]
{
    const int blocks_per_b = LTOK / TOK_PER_BLOCK;        // 72
    const int b    = blockIdx.x / blocks_per_b;
    const int tok0 = (blockIdx.x % blocks_per_b) * TOK_PER_BLOCK;
    const int warp = threadIdx.x >> 5;
    const int lane = threadIdx.x & 31;

    __shared__ float4 i_sm[DDIM / 4];                     // 4 KB
    i_sm[threadIdx.x] = ((const float4*)(ifeat + (size_t)b * DDIM))[threadIdx.x];
    __syncthreads();

    const int l = tok0 + warp;
    const float4* trow = (const float4*)(img + ((size_t)b * LTOK + l) * DDIM);

    float dot = 0.f, nt = 0.f, ni = 0.f;
#pragma unroll
    for (int it = 0; it < 8; it++) {
        int idx = it * 32 + lane;
        float4 t  = trow[idx];
        float4 iv = i_sm[idx];
        dot = fmaf(t.x, iv.x, fmaf(t.y, iv.y, fmaf(t.z, iv.z, fmaf(t.w, iv.w, dot))));
        nt  = fmaf(t.x, t.x,  fmaf(t.y, t.y,  fmaf(t.z, t.z,  fmaf(t.w, t.w,  nt))));
        ni  = fmaf(iv.x, iv.x, fmaf(iv.y, iv.y, fmaf(iv.z, iv.z, fmaf(iv.w, iv.w, ni))));
    }
#pragma unroll
    for (int o = 16; o; o >>= 1) {
        dot += __shfl_xor_sync(0xFFFFFFFFu, dot, o);
        nt  += __shfl_xor_sync(0xFFFFFFFFu, nt,  o);
        ni  += __shfl_xor_sync(0xFFFFFFFFu, ni,  o);
    }
    if (lane == 0) {
        float denom = fmaxf(sqrtf(ni) * sqrtf(nt), EPSV);
        g_sims[b * LTOK + l] = dot / denom;
    }
}

// ---------------------------------------------------------------------------
// Kernel 2: per batch element, select k smallest sims (set only — order does
// not affect the mean), then coalesced gather-mean of those k token rows.
// ---------------------------------------------------------------------------
__global__ __launch_bounds__(256) void select_mean_kernel(
    const float* __restrict__ img,     // [B, L, D]
    const int*   __restrict__ kptr,    // scalar k
    float*       __restrict__ out)     // [B, D]
{
    const int b   = blockIdx.x;
    const int tid = threadIdx.x;
    int k = *kptr;
    if (k < 1) k = 1;
    if (k > LTOK) k = LTOK;

    __shared__ float s_sims[LTOK];
    __shared__ int   s_idx[LTOK];
    __shared__ float red_v[8];
    __shared__ int   red_i[8];

    for (int i = tid; i < LTOK; i += 256) s_sims[i] = g_sims[b * LTOK + i];
    __syncthreads();

    // k rounds of block argmin with lowest-index tie-break
    for (int r = 0; r < k; r++) {
        float bv = INFINITY; int bi = 0x7FFFFFFF;
        for (int i = tid; i < LTOK; i += 256) {
            float v = s_sims[i];
            if (v < bv || (v == bv && i < bi)) { bv = v; bi = i; }
        }
#pragma unroll
        for (int o = 16; o; o >>= 1) {
            float ov = __shfl_xor_sync(0xFFFFFFFFu, bv, o);
            int   oi = __shfl_xor_sync(0xFFFFFFFFu, bi, o);
            if (ov < bv || (ov == bv && oi < bi)) { bv = ov; bi = oi; }
        }
        const int warp = tid >> 5, lane = tid & 31;
        if (lane == 0) { red_v[warp] = bv; red_i[warp] = bi; }
        __syncthreads();
        if (tid == 0) {
            float fv = red_v[0]; int fi = red_i[0];
#pragma unroll
            for (int w = 1; w < 8; w++) {
                if (red_v[w] < fv || (red_v[w] == fv && red_i[w] < fi)) {
                    fv = red_v[w]; fi = red_i[w];
                }
            }
            s_idx[r] = fi;
            s_sims[fi] = INFINITY;   // remove from candidate set
        }
        __syncthreads();
    }

    // gather-mean: thread tid owns float4 column slice [4*tid, 4*tid+4)
    float4 acc = make_float4(0.f, 0.f, 0.f, 0.f);
    for (int j = 0; j < k; j++) {
        const float4* row = (const float4*)(img + ((size_t)b * LTOK + s_idx[j]) * DDIM);
        float4 t = row[tid];
        acc.x += t.x; acc.y += t.y; acc.z += t.z; acc.w += t.w;
    }
    const float inv = 1.0f / (float)k;
    float4 r = make_float4(acc.x * inv, acc.y * inv, acc.z * inv, acc.w * inv);
    ((float4*)(out + (size_t)b * DDIM))[tid] = r;
}

extern "C" void kernel_launch(void* const* d_in, const int* in_sizes, int n_in,
                              void* d_out, int out_size)
{
    // Resolve inputs by element count (robust to metadata ordering):
    //   i_feats:     256*1024      = 262144
    //   image_feats: 256*576*1024  = 150994944
    //   k:           1
    const float* i_feats = 0;
    const float* img     = 0;
    const int*   kptr    = 0;
    for (int i = 0; i < n_in; i++) {
        if (in_sizes[i] == BATCH * DDIM)            i_feats = (const float*)d_in[i];
        else if (in_sizes[i] == BATCH * LTOK * DDIM) img    = (const float*)d_in[i];
        else                                         kptr   = (const int*)d_in[i];
    }
    float* out = (float*)d_out;

    sims_kernel<<<BATCH * (LTOK / TOK_PER_BLOCK), 256>>>(i_feats, img);
    select_mean_kernel<<<BATCH, 256>>>(img, kptr, out);
}

// round 5
// speedup vs baseline: 1.0045x; 1.0045x over previous
#include <cuda_runtime.h>
#include <math.h>

#define BATCH 256
#define LTOK  576
#define DDIM  1024
#define EPSV  1e-8f
#define TOK_PER_BLOCK 8
#define KMAX  64

// scratch
__device__ float g_sims[BATCH * LTOK];
__device__ int   g_idx[BATCH * KMAX];

// ---------------------------------------------------------------------------
// Kernel 1: cosine sims. One warp per token; 8 tokens (same batch row) per
// block so i_feats[b] is staged in smem once. Fully coalesced float4 streams.
// (Measured ~7.1 TB/s — at roofline; unchanged.)
// ---------------------------------------------------------------------------
__global__ __launch_bounds__(256) void sims_kernel(
    const float* __restrict__ ifeat,   // [B, D]
    const float* __restrict__ img)     // [B, L, D]
{
    const int blocks_per_b = LTOK / TOK_PER_BLOCK;        // 72
    const int b    = blockIdx.x / blocks_per_b;
    const int tok0 = (blockIdx.x % blocks_per_b) * TOK_PER_BLOCK;
    const int warp = threadIdx.x >> 5;
    const int lane = threadIdx.x & 31;

    __shared__ float4 i_sm[DDIM / 4];                     // 4 KB
    i_sm[threadIdx.x] = ((const float4*)(ifeat + (size_t)b * DDIM))[threadIdx.x];
    __syncthreads();

    const int l = tok0 + warp;
    const float4* trow = (const float4*)(img + ((size_t)b * LTOK + l) * DDIM);

    float dot = 0.f, nt = 0.f, ni = 0.f;
#pragma unroll
    for (int it = 0; it < 8; it++) {
        int idx = it * 32 + lane;
        float4 t  = trow[idx];
        float4 iv = i_sm[idx];
        dot = fmaf(t.x, iv.x, fmaf(t.y, iv.y, fmaf(t.z, iv.z, fmaf(t.w, iv.w, dot))));
        nt  = fmaf(t.x, t.x,  fmaf(t.y, t.y,  fmaf(t.z, t.z,  fmaf(t.w, t.w,  nt))));
        ni  = fmaf(iv.x, iv.x, fmaf(iv.y, iv.y, fmaf(iv.z, iv.z, fmaf(iv.w, iv.w, ni))));
    }
#pragma unroll
    for (int o = 16; o; o >>= 1) {
        dot += __shfl_xor_sync(0xFFFFFFFFu, dot, o);
        nt  += __shfl_xor_sync(0xFFFFFFFFu, nt,  o);
        ni  += __shfl_xor_sync(0xFFFFFFFFu, ni,  o);
    }
    if (lane == 0) {
        float denom = fmaxf(sqrtf(ni) * sqrtf(nt), EPSV);
        g_sims[b * LTOK + l] = dot / denom;
    }
}

// ---------------------------------------------------------------------------
// Kernel 2: warp-per-batch bottom-k selection, register-resident, shfl-only.
// Key = (order-preserving-uint(sim) << 10) | token_idx : min key == min sim
// with lowest-index tie-break (exactly jax top_k(-sims) semantics).
// ---------------------------------------------------------------------------
__device__ __forceinline__ unsigned long long pack_key(float v, int idx) {
    unsigned int u = __float_as_uint(v);
    u = (u & 0x80000000u) ? ~u : (u | 0x80000000u);   // monotonic float->uint
    return ((unsigned long long)u << 10) | (unsigned int)idx;
}

__global__ __launch_bounds__(256) void select_kernel(const int* __restrict__ kptr)
{
    const int warp = threadIdx.x >> 5;
    const int lane = threadIdx.x & 31;
    const int b    = blockIdx.x * 8 + warp;
    int k = *kptr;
    if (k < 1) k = 1;
    if (k > KMAX) k = KMAX;

    // 576 / 32 = 18 keys per lane
    unsigned long long keys[18];
#pragma unroll
    for (int j = 0; j < 18; j++) {
        int idx = j * 32 + lane;
        keys[j] = pack_key(g_sims[b * LTOK + idx], idx);
    }

    for (int r = 0; r < k; r++) {
        unsigned long long m = keys[0];
#pragma unroll
        for (int j = 1; j < 18; j++) m = min(m, keys[j]);
#pragma unroll
        for (int o = 16; o; o >>= 1) {
            unsigned long long om = __shfl_xor_sync(0xFFFFFFFFu, m, o);
            m = min(m, om);
        }
        if (lane == 0) g_idx[b * KMAX + r] = (int)(m & 1023u);
        // remove winner (exactly one lane/slot matches; keys are unique by idx)
#pragma unroll
        for (int j = 0; j < 18; j++)
            if (keys[j] == m) keys[j] = 0xFFFFFFFFFFFFFFFFull;
    }
}

// ---------------------------------------------------------------------------
// Kernel 3: gather-mean. grid=(BATCH, 2): each block owns a 512-float slice
// of one batch row; each thread sums its float4 over the k selected tokens
// (k independent loads in flight per thread; unroll 4 to front-batch LDGs).
// ---------------------------------------------------------------------------
__global__ __launch_bounds__(128) void mean_kernel(
    const float* __restrict__ img,     // [B, L, D]
    const int*   __restrict__ kptr,
    float*       __restrict__ out)     // [B, D]
{
    const int b     = blockIdx.x;
    const int slice = blockIdx.y;                       // 0 or 1
    const int tid   = threadIdx.x;                      // 0..127
    const int col4  = slice * 128 + tid;                // float4 column
    int k = *kptr;
    if (k < 1) k = 1;
    if (k > KMAX) k = KMAX;

    __shared__ int s_idx[KMAX];
    if (tid < k) s_idx[tid] = g_idx[b * KMAX + tid];
    __syncthreads();

    float4 acc = make_float4(0.f, 0.f, 0.f, 0.f);
#pragma unroll 4
    for (int j = 0; j < k; j++) {
        const float4* row = (const float4*)(img + ((size_t)b * LTOK + s_idx[j]) * DDIM);
        float4 t = __ldg(&row[col4]);
        acc.x += t.x; acc.y += t.y; acc.z += t.z; acc.w += t.w;
    }
    const float inv = 1.0f / (float)k;
    float4 r = make_float4(acc.x * inv, acc.y * inv, acc.z * inv, acc.w * inv);
    ((float4*)(out + (size_t)b * DDIM))[col4] = r;
}

extern "C" void kernel_launch(void* const* d_in, const int* in_sizes, int n_in,
                              void* d_out, int out_size)
{
    const float* i_feats = 0;
    const float* img     = 0;
    const int*   kptr    = 0;
    for (int i = 0; i < n_in; i++) {
        if (in_sizes[i] == BATCH * DDIM)             i_feats = (const float*)d_in[i];
        else if (in_sizes[i] == BATCH * LTOK * DDIM) img     = (const float*)d_in[i];
        else                                         kptr    = (const int*)d_in[i];
    }
    float* out = (float*)d_out;

    sims_kernel<<<BATCH * (LTOK / TOK_PER_BLOCK), 256>>>(i_feats, img);
    select_kernel<<<BATCH / 8, 256>>>(kptr);
    dim3 grid(BATCH, 2);
    mean_kernel<<<grid, 128>>>(img, kptr, out);
}